// round 10
// baseline (speedup 1.0000x reference)
#include <cuda_runtime.h>
#include <cuda_bf16.h>
#include <math.h>
#include <stdint.h>

// ---------------- problem constants ----------------
#define D_DIM 1024
#define NCOLS 256      // 240 decision + 16 gate logits
#define O_DIM 512
#define M_MAX 8192

__device__ __align__(16) __nv_bfloat16 g_B1[NCOLS * 2048];   // [hi|lo]
__device__ __align__(16) __nv_bfloat16 g_B2[O_DIM * 768];    // [hi|hi|lo]
__device__ __align__(16) float g_logits[2 * M_MAX * NCOLS];  // split-K partials
__device__ __align__(16) float g_bias[NCOLS];
__device__ float g_invtemp[240];

// ---------------- helpers ----------------
__device__ __forceinline__ uint32_t smem_u32(const void* p) {
    uint32_t a;
    asm("{ .reg .u64 t; cvta.to.shared.u64 t, %1; cvt.u32.u64 %0, t; }"
        : "=r"(a) : "l"(p));
    return a;
}
__device__ __forceinline__ void cp16(uint32_t s, const void* g) {
    asm volatile("cp.async.cg.shared.global [%0], [%1], 16;" :: "r"(s), "l"(g));
}
#define CP_COMMIT() asm volatile("cp.async.commit_group;" ::: "memory")
#define CP_WAIT(n)  asm volatile("cp.async.wait_group %0;" :: "n"(n) : "memory")

__device__ __forceinline__ void ldsm4(uint32_t r[4], uint32_t addr) {
    asm volatile("ldmatrix.sync.aligned.m8n8.x4.shared.b16 {%0,%1,%2,%3}, [%4];"
                 : "=r"(r[0]), "=r"(r[1]), "=r"(r[2]), "=r"(r[3]) : "r"(addr));
}
__device__ __forceinline__ void mma16816(float c[4], const uint32_t a[4],
                                         uint32_t b0, uint32_t b1) {
    asm volatile(
        "mma.sync.aligned.m16n8k16.row.col.f32.bf16.bf16.f32 "
        "{%0,%1,%2,%3}, {%4,%5,%6,%7}, {%8,%9}, {%0,%1,%2,%3};"
        : "+f"(c[0]), "+f"(c[1]), "+f"(c[2]), "+f"(c[3])
        : "r"(a[0]), "r"(a[1]), "r"(a[2]), "r"(a[3]), "r"(b0), "r"(b1));
}
__device__ __forceinline__ void bsplit(float v, __nv_bfloat16& h, __nv_bfloat16& l) {
    h = __float2bfloat16(v);
    l = __float2bfloat16(v - __bfloat162float(h));
}

// ================= GEMM1: fused-split x, 3-stage, one sync/iter =================
#define ROWB1  80
#define AH_OFF 0
#define AL_OFF 5120
#define BH_OFF 10240
#define BL_OFF 20480
#define STAGE1 30720
#define SMEM1  (3 * STAGE1)           // 92160 -> 2 CTAs/SM

__global__ __launch_bounds__(256, 2)
void gemm1_fused(const float* __restrict__ x, const __nv_bfloat16* __restrict__ B1,
                 float* __restrict__ Cbase, int M) {
    extern __shared__ char smem[];
    const uint32_t sb = smem_u32(smem);
    const int tid = threadIdx.x, warp = tid >> 5, lane = tid & 31;
    const int m0 = blockIdx.x * 64, n0 = blockIdx.y * 128;
    const int koff = blockIdx.z * 512;          // split-K=2
    float* C = Cbase + (size_t)blockIdx.z * M * NCOLS;
    const int wm = (warp >> 2) * 32, wn = (warp & 3) * 32;
    const int NK = 16;
    const int arow = tid >> 2, aq = tid & 3;

    float acc[2][4][4];
#pragma unroll
    for (int i = 0; i < 2; i++)
#pragma unroll
        for (int j = 0; j < 4; j++)
#pragma unroll
            for (int k = 0; k < 4; k++) acc[i][j][k] = 0.f;

    float4 fv[2];
    auto ldgA = [&](int it) {
        if (it >= NK) return;
        const float* src = x + (size_t)(m0 + arow) * D_DIM + koff + it * 32 + aq * 8;
        fv[0] = *(const float4*)(src);
        fv[1] = *(const float4*)(src + 4);
    };
    auto stsA = [&](int it) {
        if (it >= NK) return;
        uint32_t dst = sb + (it % 3) * STAGE1 + arow * ROWB1 + aq * 16;
        uint32_t ph[4], pl[4];
        const float* f = (const float*)fv;
#pragma unroll
        for (int j = 0; j < 4; j++) {
            float v0 = f[2 * j], v1 = f[2 * j + 1];
            __nv_bfloat16 h0, l0, h1, l1;
            bsplit(v0, h0, l0); bsplit(v1, h1, l1);
            __nv_bfloat162 th = __halves2bfloat162(h0, h1);
            __nv_bfloat162 tl = __halves2bfloat162(l0, l1);
            ph[j] = *(uint32_t*)&th;
            pl[j] = *(uint32_t*)&tl;
        }
        asm volatile("st.shared.v4.b32 [%0], {%1,%2,%3,%4};"
                     :: "r"(dst + AH_OFF), "r"(ph[0]), "r"(ph[1]), "r"(ph[2]), "r"(ph[3]));
        asm volatile("st.shared.v4.b32 [%0], {%1,%2,%3,%4};"
                     :: "r"(dst + AL_OFF), "r"(pl[0]), "r"(pl[1]), "r"(pl[2]), "r"(pl[3]));
    };
    auto cpB = [&](int it) {
        if (it < NK) {
            int k0 = koff + it * 32;
            uint32_t base = sb + (it % 3) * STAGE1;
#pragma unroll
            for (int i = 0; i < 2; i++) {
                int idx = tid + i * 256;
                int row = idx >> 2, s = idx & 3;
                const __nv_bfloat16* src = B1 + (size_t)(n0 + row) * 2048 + k0 + s * 8;
                cp16(base + BH_OFF + row * ROWB1 + s * 16, src);
                cp16(base + BL_OFF + row * ROWB1 + s * 16, src + 1024);
            }
        }
        CP_COMMIT();
    };

    ldgA(0); stsA(0);
    ldgA(1);
    cpB(0); cpB(1);

    for (int it = 0; it < NK; it++) {
        CP_WAIT(1);
        __syncthreads();

        stsA(it + 1);
        ldgA(it + 2);
        cpB(it + 2);

        const uint32_t sBase = sb + (it % 3) * STAGE1;
#pragma unroll
        for (int ks = 0; ks < 2; ks++) {
            const uint32_t kb = (ks * 16 + (lane >> 4) * 8) * 2;
            uint32_t ah[2][4], al[2][4], bh[2][4], bl[2][4];
#pragma unroll
            for (int mf = 0; mf < 2; mf++) {
                uint32_t ra = sBase + (wm + mf * 16 + (lane & 15)) * ROWB1 + kb;
                ldsm4(ah[mf], ra + AH_OFF);
                ldsm4(al[mf], ra + AL_OFF);
            }
#pragma unroll
            for (int nf2 = 0; nf2 < 2; nf2++) {
                uint32_t rb = sBase + (wn + nf2 * 16 + (lane & 15)) * ROWB1 + kb;
                ldsm4(bh[nf2], rb + BH_OFF);
                ldsm4(bl[nf2], rb + BL_OFF);
            }
#pragma unroll
            for (int mf = 0; mf < 2; mf++)
#pragma unroll
                for (int nf = 0; nf < 4; nf++) {
                    uint32_t h0 = bh[nf >> 1][(nf & 1) ? 1 : 0];
                    uint32_t h1 = bh[nf >> 1][(nf & 1) ? 3 : 2];
                    uint32_t l0 = bl[nf >> 1][(nf & 1) ? 1 : 0];
                    uint32_t l1 = bl[nf >> 1][(nf & 1) ? 3 : 2];
                    mma16816(acc[mf][nf], ah[mf], h0, h1);
                    mma16816(acc[mf][nf], al[mf], h0, h1);
                    mma16816(acc[mf][nf], ah[mf], l0, l1);
                }
        }
    }

#pragma unroll
    for (int mf = 0; mf < 2; mf++)
#pragma unroll
        for (int nf = 0; nf < 4; nf++) {
            int row = m0 + wm + mf * 16 + (lane >> 2);
            int col = n0 + wn + nf * 8 + 2 * (lane & 3);
            *(float2*)&C[(size_t)row * NCOLS + col] =
                make_float2(acc[mf][nf][0], acc[mf][nf][1]);
            *(float2*)&C[(size_t)(row + 8) * NCOLS + col] =
                make_float2(acc[mf][nf][2], acc[mf][nf][3]);
        }
}

// ================= MEGA v2: 32 tokens/CTA, 256 thr, BK=16, 2 CTAs/SM =================
// A (split Wl) resident in smem; B2 [hi|hi|lo] streamed, 3-stage ring.
#define G2_A    2048                     // after stats[32][8][2] = 2048 B
#define G2_AROW 1040                     // step 65 mod 8 == 1 -> conflict-free ldsm
#define G2_B0   (G2_A + 32 * G2_AROW)    // 35328
#define G2_BROW 48                       // 16 bf16 (32B) + 16B pad; step 3 mod 8
#define G2_BSTG (512 * G2_BROW)          // 24576
#define G2_SMEM (G2_B0 + 3 * G2_BSTG)    // 109056 -> 2 CTAs/SM
#define G2_NK   48                       // 768 / 16

__global__ __launch_bounds__(256, 2)
void gemm2_mega(const float* __restrict__ logits, const __nv_bfloat16* __restrict__ B2,
                const float* __restrict__ gamma, const float* __restrict__ beta,
                float* __restrict__ out, int M) {
    extern __shared__ char smem[];
    const uint32_t sb = smem_u32(smem);
    const int tid = threadIdx.x, warp = tid >> 5, lane = tid & 31;
    const int m0 = blockIdx.x * 32;
    const int wn = warp * 64;            // 8 warps x 64 cols = 512

    // ---- prologue 1: combine split-K partials + bias -> smem f32 [32][264] ----
    float* slog = (float*)(smem + G2_B0);
    {
        const float4* s0 = (const float4*)(logits + (size_t)m0 * NCOLS);
        const float4* s1 = (const float4*)(logits + (size_t)(M + m0) * NCOLS);
        const float4* bb = (const float4*)g_bias;
#pragma unroll
        for (int i = 0; i < 8; i++) {
            int j = tid + i * 256;            // 0..2047 over 32 tok x 64 float4
            int row = j >> 6, q = j & 63;
            float4 a = s0[(size_t)row * 64 + q], b = s1[(size_t)row * 64 + q], c = bb[q];
            ((float4*)(slog + row * 264))[q] =
                make_float4(a.x + b.x + c.x, a.y + b.y + c.y,
                            a.z + b.z + c.z, a.w + b.w + c.w);
        }
    }
    __syncthreads();

    // ---- prologue 2: gate softmax + sigmoids + paths -> A smem (split bf16) ----
#pragma unroll
    for (int i = 0; i < 4; i++) {
        int tok = warp * 4 + i;              // 0..31
        const float* lrow = slog + tok * 264;
        float gl = (lane < 16) ? lrow[240 + lane] : -INFINITY;
        float mx = gl;
#pragma unroll
        for (int o = 16; o > 0; o >>= 1) mx = fmaxf(mx, __shfl_xor_sync(0xffffffffu, mx, o));
        float e = (lane < 16) ? expf(gl - mx) : 0.f;
        float s = e;
#pragma unroll
        for (int o = 16; o > 0; o >>= 1) s += __shfl_xor_sync(0xffffffffu, s, o);
        float gate = e / s;

        if (lane < 16) {
            int t = lane;
            float dec[15];
#pragma unroll
            for (int n = 0; n < 15; n++) {
                float z = lrow[t * 15 + n] * g_invtemp[t * 15 + n];
                dec[n] = 1.f / (1.f + expf(-z));
            }
            __nv_bfloat162 hi[8], lo[8];
#pragma unroll
            for (int leaf = 0; leaf < 16; leaf += 2) {
                __nv_bfloat16 h[2], l[2];
#pragma unroll
                for (int q2 = 0; q2 < 2; q2++) {
                    int lf = leaf + q2;
                    float p = gate;
                    int node = 0;
#pragma unroll
                    for (int d = 0; d < 4; d++) {
                        int bit = (lf >> (3 - d)) & 1;
                        float dv = dec[node];
                        p *= bit ? (1.f - dv) : dv;
                        node = 2 * node + 1 + bit;
                    }
                    bsplit(p, h[q2], l[q2]);
                }
                hi[leaf >> 1] = __halves2bfloat162(h[0], h[1]);
                lo[leaf >> 1] = __halves2bfloat162(l[0], l[1]);
            }
            char* arow = smem + G2_A + tok * G2_AROW + t * 32;
            *(uint4*)(arow)             = ((uint4*)hi)[0];
            *(uint4*)(arow + 16)        = ((uint4*)hi)[1];
            *(uint4*)(arow + 512)       = ((uint4*)lo)[0];
            *(uint4*)(arow + 512 + 16)  = ((uint4*)lo)[1];
        }
    }
    __syncthreads();   // slog dead; A ready

    // ---- main loop: stream B2 (K'=768, BK=16, 3-stage ring, one sync/iter) ----
    float acc[2][8][4];
#pragma unroll
    for (int i = 0; i < 2; i++)
#pragma unroll
        for (int j = 0; j < 8; j++)
#pragma unroll
            for (int k = 0; k < 4; k++) acc[i][j][k] = 0.f;

    auto cpB = [&](int it) {
        if (it < G2_NK) {
            int k0 = it * 16;
            uint32_t bB = sb + G2_B0 + (it % 3) * G2_BSTG;
#pragma unroll
            for (int i = 0; i < 4; i++) {
                int idx = tid + i * 256;       // 0..1023: 512 rows x 2 segs
                int row = idx >> 1, s = idx & 1;
                cp16(bB + row * G2_BROW + s * 16, B2 + (size_t)row * 768 + k0 + s * 8);
            }
        }
        CP_COMMIT();
    };

    cpB(0); cpB(1);

    for (int it = 0; it < G2_NK; it++) {
        CP_WAIT(1);
        __syncthreads();
        cpB(it + 2);

        const uint32_t bB = sb + G2_B0 + (it % 3) * G2_BSTG;
        int k = it * 16;
        int ka = (k < 512) ? k : k - 512;    // 3rd B segment reuses A-hi
        uint32_t ah[2][4], br[4][4];
        uint32_t ra = sb + G2_A + (lane & 15) * G2_AROW + (ka + (lane >> 4) * 8) * 2;
        ldsm4(ah[0], ra);
        ldsm4(ah[1], ra + 16 * G2_AROW);
        uint32_t kb = ((lane >> 4) * 8) * 2;
#pragma unroll
        for (int nf2 = 0; nf2 < 4; nf2++)
            ldsm4(br[nf2], bB + (wn + nf2 * 16 + (lane & 15)) * G2_BROW + kb);
#pragma unroll
        for (int mf = 0; mf < 2; mf++)
#pragma unroll
            for (int nf = 0; nf < 8; nf++) {
                uint32_t b0 = br[nf >> 1][(nf & 1) ? 1 : 0];
                uint32_t b1 = br[nf >> 1][(nf & 1) ? 3 : 2];
                mma16816(acc[mf][nf], ah[mf], b0, b1);
            }
    }

    // ---- epilogue: fused LayerNorm over N=512 ----
    __syncthreads();
    float* stats = (float*)smem;   // [32][8][2]
#pragma unroll
    for (int i = 0; i < 4; i++) {
        int mf = i >> 1, half = i & 1;
        float s = 0.f, q = 0.f;
#pragma unroll
        for (int nf = 0; nf < 8; nf++) {
            float v0 = acc[mf][nf][half * 2 + 0], v1 = acc[mf][nf][half * 2 + 1];
            s += v0 + v1; q += v0 * v0 + v1 * v1;
        }
        s += __shfl_xor_sync(0xffffffffu, s, 1); q += __shfl_xor_sync(0xffffffffu, q, 1);
        s += __shfl_xor_sync(0xffffffffu, s, 2); q += __shfl_xor_sync(0xffffffffu, q, 2);
        if ((lane & 3) == 0) {
            int row = mf * 16 + half * 8 + (lane >> 2);
            stats[(row * 8 + warp) * 2 + 0] = s;
            stats[(row * 8 + warp) * 2 + 1] = q;
        }
    }
    __syncthreads();

#pragma unroll
    for (int i = 0; i < 4; i++) {
        int mf = i >> 1, half = i & 1;
        int row = mf * 16 + half * 8 + (lane >> 2);
        float s = 0.f, q = 0.f;
#pragma unroll
        for (int w8 = 0; w8 < 8; w8++) {
            s += stats[(row * 8 + w8) * 2 + 0];
            q += stats[(row * 8 + w8) * 2 + 1];
        }
        float mu = s * (1.f / 512.f);
        float var = q * (1.f / 512.f) - mu * mu;
        float istd = rsqrtf(var + 1e-5f);
        float* orow = out + (size_t)(m0 + row) * O_DIM;
#pragma unroll
        for (int nf = 0; nf < 8; nf++) {
            int col = wn + nf * 8 + 2 * (lane & 3);
            float2 g2 = __ldg((const float2*)&gamma[col]);
            float2 b2 = __ldg((const float2*)&beta[col]);
            float v0 = (acc[mf][nf][half * 2 + 0] - mu) * istd * g2.x + b2.x;
            float v1 = (acc[mf][nf][half * 2 + 1] - mu) * istd * g2.y + b2.y;
            *(float2*)&orow[col] = make_float2(v0, v1);
        }
    }
}

// ---------------- pack weights (coalesced leaf transpose via smem) ----------------
__global__ void pack_weights(const float* __restrict__ dw, const float* __restrict__ db,
                             const float* __restrict__ leaf, const float* __restrict__ gw,
                             const float* __restrict__ gb, const float* __restrict__ ntl) {
    const int bid = blockIdx.x;
    if (bid < 128) {
        __shared__ float tile[32][33];
        int bk = (bid & 7) * 32;
        int bo = (bid >> 3) * 32;
        int ti = threadIdx.x & 31, tj = threadIdx.x >> 5;
#pragma unroll
        for (int r = tj; r < 32; r += 8)
            tile[r][ti] = leaf[(size_t)(bk + r) * O_DIM + bo + ti];
        __syncthreads();
#pragma unroll
        for (int r = tj; r < 32; r += 8) {
            int o = bo + r, k = bk + ti;
            __nv_bfloat16 h, l; bsplit(tile[ti][r], h, l);
            size_t base = (size_t)o * 768;
            g_B2[base + k] = h; g_B2[base + 256 + k] = h; g_B2[base + 512 + k] = l;
        }
        if (bid == 0 && threadIdx.x < 240) {
            int i = threadIdx.x;
            g_bias[i] = db[i];
            float z = ntl[i] + 0.5413f;
            float sp = (z > 20.f) ? z : log1pf(expf(z));
            g_invtemp[i] = 1.0f / sp;
        } else if (bid == 1 && threadIdx.x < 16) {
            g_bias[240 + threadIdx.x] = gb[threadIdx.x];
        }
        return;
    }
    int tid = (bid - 128) * blockDim.x + threadIdx.x;
    int stride = (gridDim.x - 128) * blockDim.x;
    for (int i = tid; i < 240 * D_DIM; i += stride) {
        int n = i >> 10, d = i & 1023;
        __nv_bfloat16 h, l; bsplit(dw[i], h, l);
        size_t r = (size_t)n * 2048;
        g_B1[r + d] = h; g_B1[r + 1024 + d] = l;
    }
    for (int i = tid; i < 16 * D_DIM; i += stride) {
        int t = i >> 10, d = i & 1023;
        __nv_bfloat16 h, l; bsplit(gw[d * 16 + t], h, l);
        size_t r = (size_t)(240 + t) * 2048;
        g_B1[r + d] = h; g_B1[r + 1024 + d] = l;
    }
}

// ---------------- launch ----------------
extern "C" void kernel_launch(void* const* d_in, const int* in_sizes, int n_in,
                              void* d_out, int out_size) {
    const float* x     = (const float*)d_in[0];
    const float* dw    = (const float*)d_in[1];
    const float* db    = (const float*)d_in[2];
    const float* leaf  = (const float*)d_in[3];
    const float* gw    = (const float*)d_in[4];
    const float* gb    = (const float*)d_in[5];
    const float* ntl   = (const float*)d_in[6];
    const float* gamma = (const float*)d_in[7];
    const float* beta  = (const float*)d_in[8];
    float* out = (float*)d_out;

    int M = in_sizes[0] / D_DIM;   // 8192

    void *pB1, *pB2, *pLogits;
    cudaGetSymbolAddress(&pB1, g_B1);
    cudaGetSymbolAddress(&pB2, g_B2);
    cudaGetSymbolAddress(&pLogits, g_logits);

    static bool attr_set = false;
    if (!attr_set) {
        cudaFuncSetAttribute(gemm1_fused, cudaFuncAttributeMaxDynamicSharedMemorySize,
                             SMEM1);
        cudaFuncSetAttribute(gemm2_mega, cudaFuncAttributeMaxDynamicSharedMemorySize,
                             G2_SMEM);
        attr_set = true;
    }

    // 0) weight packing
    pack_weights<<<1024, 256>>>(dw, db, leaf, gw, gb, ntl);

    // 1) GEMM1 (fused split of x), split-K=2 -> partials
    gemm1_fused<<<dim3(M / 64, 2, 2), 256, SMEM1>>>(
        x, (const __nv_bfloat16*)pB1, (float*)pLogits, M);

    // 2) MEGA v2: combine + gate/tree + GEMM2 + LayerNorm -> out (2 CTAs/SM)
    gemm2_mega<<<M / 32, 256, G2_SMEM>>>(
        (const float*)pLogits, (const __nv_bfloat16*)pB2, gamma, beta, out, M);
}

// round 11
// speedup vs baseline: 1.2490x; 1.2490x over previous
#include <cuda_runtime.h>
#include <cuda_bf16.h>
#include <math.h>
#include <stdint.h>

// ---------------- problem constants ----------------
#define D_DIM 1024
#define NCOLS 256      // 240 decision + 16 gate logits
#define O_DIM 512
#define M_MAX 8192

__device__ __align__(16) __nv_bfloat16 g_B1[NCOLS * 2048];   // [hi|lo]
__device__ __align__(16) __nv_bfloat16 g_B2[O_DIM * 512];    // [hi|lo] compact
__device__ __align__(16) float g_logits[2 * M_MAX * NCOLS];  // split-K partials
__device__ __align__(16) float g_bias[NCOLS];
__device__ float g_invtemp[240];

// ---------------- helpers ----------------
__device__ __forceinline__ uint32_t smem_u32(const void* p) {
    uint32_t a;
    asm("{ .reg .u64 t; cvta.to.shared.u64 t, %1; cvt.u32.u64 %0, t; }"
        : "=r"(a) : "l"(p));
    return a;
}
__device__ __forceinline__ void cp16(uint32_t s, const void* g) {
    asm volatile("cp.async.cg.shared.global [%0], [%1], 16;" :: "r"(s), "l"(g));
}
#define CP_COMMIT() asm volatile("cp.async.commit_group;" ::: "memory")
#define CP_WAIT(n)  asm volatile("cp.async.wait_group %0;" :: "n"(n) : "memory")

__device__ __forceinline__ void ldsm4(uint32_t r[4], uint32_t addr) {
    asm volatile("ldmatrix.sync.aligned.m8n8.x4.shared.b16 {%0,%1,%2,%3}, [%4];"
                 : "=r"(r[0]), "=r"(r[1]), "=r"(r[2]), "=r"(r[3]) : "r"(addr));
}
__device__ __forceinline__ void mma16816(float c[4], const uint32_t a[4],
                                         uint32_t b0, uint32_t b1) {
    asm volatile(
        "mma.sync.aligned.m16n8k16.row.col.f32.bf16.bf16.f32 "
        "{%0,%1,%2,%3}, {%4,%5,%6,%7}, {%8,%9}, {%0,%1,%2,%3};"
        : "+f"(c[0]), "+f"(c[1]), "+f"(c[2]), "+f"(c[3])
        : "r"(a[0]), "r"(a[1]), "r"(a[2]), "r"(a[3]), "r"(b0), "r"(b1));
}
__device__ __forceinline__ void bsplit(float v, __nv_bfloat16& h, __nv_bfloat16& l) {
    h = __float2bfloat16(v);
    l = __float2bfloat16(v - __bfloat162float(h));
}

// ================= GEMM1: fused-split x, 3-stage, one sync/iter =================
#define ROWB1  80
#define AH_OFF 0
#define AL_OFF 5120
#define BH_OFF 10240
#define BL_OFF 20480
#define STAGE1 30720
#define SMEM1  (3 * STAGE1)           // 92160 -> 2 CTAs/SM

__global__ __launch_bounds__(256, 2)
void gemm1_fused(const float* __restrict__ x, const __nv_bfloat16* __restrict__ B1,
                 float* __restrict__ Cbase, int M) {
    extern __shared__ char smem[];
    const uint32_t sb = smem_u32(smem);
    const int tid = threadIdx.x, warp = tid >> 5, lane = tid & 31;
    const int m0 = blockIdx.x * 64, n0 = blockIdx.y * 128;
    const int koff = blockIdx.z * 512;          // split-K=2
    float* C = Cbase + (size_t)blockIdx.z * M * NCOLS;
    const int wm = (warp >> 2) * 32, wn = (warp & 3) * 32;
    const int NK = 16;
    const int arow = tid >> 2, aq = tid & 3;

    float acc[2][4][4];
#pragma unroll
    for (int i = 0; i < 2; i++)
#pragma unroll
        for (int j = 0; j < 4; j++)
#pragma unroll
            for (int k = 0; k < 4; k++) acc[i][j][k] = 0.f;

    float4 fv[2];
    auto ldgA = [&](int it) {
        if (it >= NK) return;
        const float* src = x + (size_t)(m0 + arow) * D_DIM + koff + it * 32 + aq * 8;
        fv[0] = *(const float4*)(src);
        fv[1] = *(const float4*)(src + 4);
    };
    auto stsA = [&](int it) {
        if (it >= NK) return;
        uint32_t dst = sb + (it % 3) * STAGE1 + arow * ROWB1 + aq * 16;
        uint32_t ph[4], pl[4];
        const float* f = (const float*)fv;
#pragma unroll
        for (int j = 0; j < 4; j++) {
            float v0 = f[2 * j], v1 = f[2 * j + 1];
            __nv_bfloat16 h0, l0, h1, l1;
            bsplit(v0, h0, l0); bsplit(v1, h1, l1);
            __nv_bfloat162 th = __halves2bfloat162(h0, h1);
            __nv_bfloat162 tl = __halves2bfloat162(l0, l1);
            ph[j] = *(uint32_t*)&th;
            pl[j] = *(uint32_t*)&tl;
        }
        asm volatile("st.shared.v4.b32 [%0], {%1,%2,%3,%4};"
                     :: "r"(dst + AH_OFF), "r"(ph[0]), "r"(ph[1]), "r"(ph[2]), "r"(ph[3]));
        asm volatile("st.shared.v4.b32 [%0], {%1,%2,%3,%4};"
                     :: "r"(dst + AL_OFF), "r"(pl[0]), "r"(pl[1]), "r"(pl[2]), "r"(pl[3]));
    };
    auto cpB = [&](int it) {
        if (it < NK) {
            int k0 = koff + it * 32;
            uint32_t base = sb + (it % 3) * STAGE1;
#pragma unroll
            for (int i = 0; i < 2; i++) {
                int idx = tid + i * 256;
                int row = idx >> 2, s = idx & 3;
                const __nv_bfloat16* src = B1 + (size_t)(n0 + row) * 2048 + k0 + s * 8;
                cp16(base + BH_OFF + row * ROWB1 + s * 16, src);
                cp16(base + BL_OFF + row * ROWB1 + s * 16, src + 1024);
            }
        }
        CP_COMMIT();
    };

    ldgA(0); stsA(0);
    ldgA(1);
    cpB(0); cpB(1);

    for (int it = 0; it < NK; it++) {
        CP_WAIT(1);
        __syncthreads();

        stsA(it + 1);
        ldgA(it + 2);
        cpB(it + 2);

        const uint32_t sBase = sb + (it % 3) * STAGE1;
#pragma unroll
        for (int ks = 0; ks < 2; ks++) {
            const uint32_t kb = (ks * 16 + (lane >> 4) * 8) * 2;
            uint32_t ah[2][4], al[2][4], bh[2][4], bl[2][4];
#pragma unroll
            for (int mf = 0; mf < 2; mf++) {
                uint32_t ra = sBase + (wm + mf * 16 + (lane & 15)) * ROWB1 + kb;
                ldsm4(ah[mf], ra + AH_OFF);
                ldsm4(al[mf], ra + AL_OFF);
            }
#pragma unroll
            for (int nf2 = 0; nf2 < 2; nf2++) {
                uint32_t rb = sBase + (wn + nf2 * 16 + (lane & 15)) * ROWB1 + kb;
                ldsm4(bh[nf2], rb + BH_OFF);
                ldsm4(bl[nf2], rb + BL_OFF);
            }
#pragma unroll
            for (int mf = 0; mf < 2; mf++)
#pragma unroll
                for (int nf = 0; nf < 4; nf++) {
                    uint32_t h0 = bh[nf >> 1][(nf & 1) ? 1 : 0];
                    uint32_t h1 = bh[nf >> 1][(nf & 1) ? 3 : 2];
                    uint32_t l0 = bl[nf >> 1][(nf & 1) ? 1 : 0];
                    uint32_t l1 = bl[nf >> 1][(nf & 1) ? 3 : 2];
                    mma16816(acc[mf][nf], ah[mf], h0, h1);
                    mma16816(acc[mf][nf], al[mf], h0, h1);
                    mma16816(acc[mf][nf], ah[mf], l0, l1);
                }
        }
    }

#pragma unroll
    for (int mf = 0; mf < 2; mf++)
#pragma unroll
        for (int nf = 0; nf < 4; nf++) {
            int row = m0 + wm + mf * 16 + (lane >> 2);
            int col = n0 + wn + nf * 8 + 2 * (lane & 3);
            *(float2*)&C[(size_t)row * NCOLS + col] =
                make_float2(acc[mf][nf][0], acc[mf][nf][1]);
            *(float2*)&C[(size_t)(row + 8) * NCOLS + col] =
                make_float2(acc[mf][nf][2], acc[mf][nf][3]);
        }
}

// ================= MEGA: 64 tokens/CTA, compact B2 [hi|lo], B-reuse in regs =================
// iters 0-7 (B-hi tiles): ah*bh + al*bh; iters 8-15 (B-lo tiles): ah*bl.
#define G2_A    4096                     // after stats[64][8][2]
#define G2_AROW 1040                     // 512 cols [ah|al] + 16 B pad
#define G2_B0   (4096 + 64 * 1040)       // 70656
#define G2_BROW 80                       // 32 bf16 + 16 B pad (step 5 mod 8)
#define G2_BSTG (512 * G2_BROW)          // 40960
#define G2_SMEM (G2_B0 + 3 * G2_BSTG)    // 193536
#define G2_NK   16                       // 512 B-cols / 32

__global__ __launch_bounds__(512)
void gemm2_mega(const float* __restrict__ logits, const __nv_bfloat16* __restrict__ B2,
                const float* __restrict__ gamma, const float* __restrict__ beta,
                float* __restrict__ out, int M) {
    extern __shared__ char smem[];
    const uint32_t sb = smem_u32(smem);
    const int tid = threadIdx.x, warp = tid >> 5, lane = tid & 31;
    const int m0 = blockIdx.x * 64;
    const int wm = (warp >> 3) * 32, wn = (warp & 7) * 64;

    // ---- prologue 1: combine split-K partials + bias -> smem f32 [64][264] ----
    float* slog = (float*)(smem + G2_B0);
    {
        const float4* s0 = (const float4*)(logits + (size_t)m0 * NCOLS);
        const float4* s1 = (const float4*)(logits + (size_t)(M + m0) * NCOLS);
        const float4* bb = (const float4*)g_bias;
#pragma unroll
        for (int i = 0; i < 8; i++) {
            int j = tid + i * 512;
            int row = j >> 6, q = j & 63;
            float4 a = s0[(size_t)row * 64 + q], b = s1[(size_t)row * 64 + q], c = bb[q];
            ((float4*)(slog + row * 264))[q] =
                make_float4(a.x + b.x + c.x, a.y + b.y + c.y,
                            a.z + b.z + c.z, a.w + b.w + c.w);
        }
    }
    __syncthreads();

    // ---- prologue 2: gate softmax + sigmoids + paths -> A smem [ah|al] ----
#pragma unroll
    for (int i = 0; i < 4; i++) {
        int tok = warp * 4 + i;
        const float* lrow = slog + tok * 264;
        float gl = (lane < 16) ? lrow[240 + lane] : -INFINITY;
        float mx = gl;
#pragma unroll
        for (int o = 16; o > 0; o >>= 1) mx = fmaxf(mx, __shfl_xor_sync(0xffffffffu, mx, o));
        float e = (lane < 16) ? expf(gl - mx) : 0.f;
        float s = e;
#pragma unroll
        for (int o = 16; o > 0; o >>= 1) s += __shfl_xor_sync(0xffffffffu, s, o);
        float gate = e / s;

        if (lane < 16) {
            int t = lane;
            float dec[15];
#pragma unroll
            for (int n = 0; n < 15; n++) {
                float z = lrow[t * 15 + n] * g_invtemp[t * 15 + n];
                dec[n] = 1.f / (1.f + expf(-z));
            }
            __nv_bfloat162 hi[8], lo[8];
#pragma unroll
            for (int leaf = 0; leaf < 16; leaf += 2) {
                __nv_bfloat16 h[2], l[2];
#pragma unroll
                for (int q2 = 0; q2 < 2; q2++) {
                    int lf = leaf + q2;
                    float p = gate;
                    int node = 0;
#pragma unroll
                    for (int d = 0; d < 4; d++) {
                        int bit = (lf >> (3 - d)) & 1;
                        float dv = dec[node];
                        p *= bit ? (1.f - dv) : dv;
                        node = 2 * node + 1 + bit;
                    }
                    bsplit(p, h[q2], l[q2]);
                }
                hi[leaf >> 1] = __halves2bfloat162(h[0], h[1]);
                lo[leaf >> 1] = __halves2bfloat162(l[0], l[1]);
            }
            char* arow = smem + G2_A + tok * G2_AROW + t * 32;
            *(uint4*)(arow)             = ((uint4*)hi)[0];
            *(uint4*)(arow + 16)        = ((uint4*)hi)[1];
            *(uint4*)(arow + 512)       = ((uint4*)lo)[0];   // al at byte 512+
            *(uint4*)(arow + 512 + 16)  = ((uint4*)lo)[1];
        }
    }
    __syncthreads();   // slog dead; A ready

    // ---- main loop: stream compact B2 (512 cols, BK=32, 3-stage, 1 sync/iter) ----
    float acc[2][8][4];
#pragma unroll
    for (int i = 0; i < 2; i++)
#pragma unroll
        for (int j = 0; j < 8; j++)
#pragma unroll
            for (int k = 0; k < 4; k++) acc[i][j][k] = 0.f;

    auto cpB = [&](int it) {
        if (it < G2_NK) {
            int k0 = it * 32;
            uint32_t bB = sb + G2_B0 + (it % 3) * G2_BSTG;
#pragma unroll
            for (int i = 0; i < 4; i++) {
                int idx = tid + i * 512;       // 2048: 512 rows x 4 segs
                int row = idx >> 2, s = idx & 3;
                cp16(bB + row * G2_BROW + s * 16, B2 + (size_t)row * 512 + k0 + s * 8);
            }
        }
        CP_COMMIT();
    };

    cpB(0); cpB(1);

    for (int it = 0; it < G2_NK; it++) {
        CP_WAIT(1);
        __syncthreads();
        cpB(it + 2);

        const uint32_t bB = sb + G2_B0 + (it % 3) * G2_BSTG;
        const bool isHi = (it < 8);           // uniform branch
#pragma unroll
        for (int ks = 0; ks < 2; ks++) {
            int kb = it * 32 + ks * 16;       // B col base
            uint32_t br[4][4];
            uint32_t kloc = (ks * 16 + (lane >> 4) * 8) * 2;
#pragma unroll
            for (int nf2 = 0; nf2 < 4; nf2++)
                ldsm4(br[nf2], bB + (wn + nf2 * 16 + (lane & 15)) * G2_BROW + kloc);

            int ka = isHi ? kb : kb - 256;    // ah cols 0-255
            uint32_t ra = sb + G2_A + (lane & 15) * G2_AROW + (ka + (lane >> 4) * 8) * 2;
            uint32_t ah[2][4];
            ldsm4(ah[0], ra + wm * G2_AROW);
            ldsm4(ah[1], ra + (wm + 16) * G2_AROW);
#pragma unroll
            for (int mf = 0; mf < 2; mf++)
#pragma unroll
                for (int nf = 0; nf < 8; nf++) {
                    uint32_t b0 = br[nf >> 1][(nf & 1) ? 1 : 0];
                    uint32_t b1 = br[nf >> 1][(nf & 1) ? 3 : 2];
                    mma16816(acc[mf][nf], ah[mf], b0, b1);
                }
            if (isHi) {                       // second term: al * bh (B reused)
                uint32_t al[2][4];
                ldsm4(al[0], ra + wm * G2_AROW + 512);
                ldsm4(al[1], ra + (wm + 16) * G2_AROW + 512);
#pragma unroll
                for (int mf = 0; mf < 2; mf++)
#pragma unroll
                    for (int nf = 0; nf < 8; nf++) {
                        uint32_t b0 = br[nf >> 1][(nf & 1) ? 1 : 0];
                        uint32_t b1 = br[nf >> 1][(nf & 1) ? 3 : 2];
                        mma16816(acc[mf][nf], al[mf], b0, b1);
                    }
            }
        }
    }

    // ---- epilogue: fused LayerNorm over N=512 ----
    __syncthreads();
    float* stats = (float*)smem;   // [64][8][2]
#pragma unroll
    for (int i = 0; i < 4; i++) {
        int mf = i >> 1, half = i & 1;
        float s = 0.f, q = 0.f;
#pragma unroll
        for (int nf = 0; nf < 8; nf++) {
            float v0 = acc[mf][nf][half * 2 + 0], v1 = acc[mf][nf][half * 2 + 1];
            s += v0 + v1; q += v0 * v0 + v1 * v1;
        }
        s += __shfl_xor_sync(0xffffffffu, s, 1); q += __shfl_xor_sync(0xffffffffu, q, 1);
        s += __shfl_xor_sync(0xffffffffu, s, 2); q += __shfl_xor_sync(0xffffffffu, q, 2);
        if ((lane & 3) == 0) {
            int row = wm + mf * 16 + half * 8 + (lane >> 2);
            stats[(row * 8 + (warp & 7)) * 2 + 0] = s;
            stats[(row * 8 + (warp & 7)) * 2 + 1] = q;
        }
    }
    __syncthreads();

#pragma unroll
    for (int i = 0; i < 4; i++) {
        int mf = i >> 1, half = i & 1;
        int row = wm + mf * 16 + half * 8 + (lane >> 2);
        float s = 0.f, q = 0.f;
#pragma unroll
        for (int w8 = 0; w8 < 8; w8++) {
            s += stats[(row * 8 + w8) * 2 + 0];
            q += stats[(row * 8 + w8) * 2 + 1];
        }
        float mu = s * (1.f / 512.f);
        float var = q * (1.f / 512.f) - mu * mu;
        float istd = rsqrtf(var + 1e-5f);
        float* orow = out + (size_t)(m0 + row) * O_DIM;
#pragma unroll
        for (int nf = 0; nf < 8; nf++) {
            int col = wn + nf * 8 + 2 * (lane & 3);
            float2 g2 = __ldg((const float2*)&gamma[col]);
            float2 b2 = __ldg((const float2*)&beta[col]);
            float v0 = (acc[mf][nf][half * 2 + 0] - mu) * istd * g2.x + b2.x;
            float v1 = (acc[mf][nf][half * 2 + 1] - mu) * istd * g2.y + b2.y;
            *(float2*)&orow[col] = make_float2(v0, v1);
        }
    }
}

// ---------------- pack weights (coalesced leaf transpose via smem) ----------------
__global__ void pack_weights(const float* __restrict__ dw, const float* __restrict__ db,
                             const float* __restrict__ leaf, const float* __restrict__ gw,
                             const float* __restrict__ gb, const float* __restrict__ ntl) {
    const int bid = blockIdx.x;
    if (bid < 128) {
        __shared__ float tile[32][33];
        int bk = (bid & 7) * 32;
        int bo = (bid >> 3) * 32;
        int ti = threadIdx.x & 31, tj = threadIdx.x >> 5;
#pragma unroll
        for (int r = tj; r < 32; r += 8)
            tile[r][ti] = leaf[(size_t)(bk + r) * O_DIM + bo + ti];
        __syncthreads();
#pragma unroll
        for (int r = tj; r < 32; r += 8) {
            int o = bo + r, k = bk + ti;
            __nv_bfloat16 h, l; bsplit(tile[ti][r], h, l);
            size_t base = (size_t)o * 512;
            g_B2[base + k] = h; g_B2[base + 256 + k] = l;
        }
        if (bid == 0 && threadIdx.x < 240) {
            int i = threadIdx.x;
            g_bias[i] = db[i];
            float z = ntl[i] + 0.5413f;
            float sp = (z > 20.f) ? z : log1pf(expf(z));
            g_invtemp[i] = 1.0f / sp;
        } else if (bid == 1 && threadIdx.x < 16) {
            g_bias[240 + threadIdx.x] = gb[threadIdx.x];
        }
        return;
    }
    int tid = (bid - 128) * blockDim.x + threadIdx.x;
    int stride = (gridDim.x - 128) * blockDim.x;
    for (int i = tid; i < 240 * D_DIM; i += stride) {
        int n = i >> 10, d = i & 1023;
        __nv_bfloat16 h, l; bsplit(dw[i], h, l);
        size_t r = (size_t)n * 2048;
        g_B1[r + d] = h; g_B1[r + 1024 + d] = l;
    }
    for (int i = tid; i < 16 * D_DIM; i += stride) {
        int t = i >> 10, d = i & 1023;
        __nv_bfloat16 h, l; bsplit(gw[d * 16 + t], h, l);
        size_t r = (size_t)(240 + t) * 2048;
        g_B1[r + d] = h; g_B1[r + 1024 + d] = l;
    }
}

// ---------------- launch ----------------
extern "C" void kernel_launch(void* const* d_in, const int* in_sizes, int n_in,
                              void* d_out, int out_size) {
    const float* x     = (const float*)d_in[0];
    const float* dw    = (const float*)d_in[1];
    const float* db    = (const float*)d_in[2];
    const float* leaf  = (const float*)d_in[3];
    const float* gw    = (const float*)d_in[4];
    const float* gb    = (const float*)d_in[5];
    const float* ntl   = (const float*)d_in[6];
    const float* gamma = (const float*)d_in[7];
    const float* beta  = (const float*)d_in[8];
    float* out = (float*)d_out;

    int M = in_sizes[0] / D_DIM;   // 8192

    void *pB1, *pB2, *pLogits;
    cudaGetSymbolAddress(&pB1, g_B1);
    cudaGetSymbolAddress(&pB2, g_B2);
    cudaGetSymbolAddress(&pLogits, g_logits);

    static bool attr_set = false;
    if (!attr_set) {
        cudaFuncSetAttribute(gemm1_fused, cudaFuncAttributeMaxDynamicSharedMemorySize,
                             SMEM1);
        cudaFuncSetAttribute(gemm2_mega, cudaFuncAttributeMaxDynamicSharedMemorySize,
                             G2_SMEM);
        attr_set = true;
    }

    // 0) weight packing
    pack_weights<<<1024, 256>>>(dw, db, leaf, gw, gb, ntl);

    // 1) GEMM1 (fused split of x), split-K=2 -> partials
    gemm1_fused<<<dim3(M / 64, 2, 2), 256, SMEM1>>>(
        x, (const __nv_bfloat16*)pB1, (float*)pLogits, M);

    // 2) MEGA: combine + gate/tree + GEMM2 (compact B2, reg-level B reuse) + LN
    gemm2_mega<<<M / 64, 512, G2_SMEM>>>(
        (const float*)pLogits, (const __nv_bfloat16*)pB2, gamma, beta, out, M);
}